// round 2
// baseline (speedup 1.0000x reference)
#include <cuda_runtime.h>
#include <cuda_bf16.h>
#include <stdint.h>

// Problem constants: N=100000 nodes, F=128 feat, R=4 relations, E=1600000, L=2.
#define NN 100000
#define FF 128
#define RR 4
#define EE 1600000
#define LL 2

// Scratch (device globals: sanctioned no-cudaMalloc workaround).
__device__ float g_aggsum[(size_t)RR * NN * FF];  // [r][n][f] feature sums
__device__ float g_cnt[(size_t)RR * NN];          // [r][n] edge counts
__device__ float g_xbuf[(size_t)NN * FF];         // inter-layer activations

// ---------------------------------------------------------------------------
__global__ void zero_kernel() {
    const size_t stride = (size_t)gridDim.x * blockDim.x;
    size_t i = (size_t)blockIdx.x * blockDim.x + threadIdx.x;
    const size_t tot4 = (size_t)RR * NN * FF / 4;
    float4 z = make_float4(0.f, 0.f, 0.f, 0.f);
    float4* agg4 = reinterpret_cast<float4*>(g_aggsum);
    for (size_t p = i; p < tot4; p += stride) agg4[p] = z;
    const size_t totc = (size_t)RR * NN;
    for (size_t p = i; p < totc; p += stride) g_cnt[p] = 0.f;
}

// ---------------------------------------------------------------------------
// Edge scatter: one warp per edge. Indices are INT32 (JAX x64-disabled default).
// ---------------------------------------------------------------------------
__global__ void scatter_kernel(const float* __restrict__ xin,
                               const int* __restrict__ ei,
                               const int* __restrict__ et) {
    const float* __restrict__ x = xin ? xin : g_xbuf;
    int warp = (int)(((size_t)blockIdx.x * blockDim.x + threadIdx.x) >> 5);
    int lane = threadIdx.x & 31;
    if (warp >= EE) return;

    int src = __ldg(&ei[warp]);
    int dst = __ldg(&ei[EE + warp]);
    int r   = __ldg(&et[warp]);

    const float4* xs = reinterpret_cast<const float4*>(x + (size_t)src * FF);
    float* dp = g_aggsum + ((size_t)r * NN + dst) * FF;

    float4 v = __ldg(xs + lane);  // 32 lanes * 4 floats = 128 features
    int c = lane * 4;
    atomicAdd(dp + c + 0, v.x);
    atomicAdd(dp + c + 1, v.y);
    atomicAdd(dp + c + 2, v.z);
    atomicAdd(dp + c + 3, v.w);

    if (lane == 0) atomicAdd(&g_cnt[(size_t)r * NN + dst], 1.0f);
}

// ---------------------------------------------------------------------------
// Fused mean + GEMM + root + bias + relu:
//   out[n,:] = relu( sum_r (agg_r[n,:]/max(cnt_r[n],1)) @ W_r + x[n,:] @ root + bias )
// One [N,640] x [640,128] GEMM; virtual K = 5 segments of 128 (4 relations +
// root), per-row mean scaling folded into A-tile loads.
// BM=128, BN=128, BK=16, 256 threads, 8x8 microtile.
// ---------------------------------------------------------------------------
__global__ __launch_bounds__(256, 2)
void gemm_kernel(const float* __restrict__ xin_p,
                 const float* __restrict__ W,      // [R, F, F] this layer
                 const float* __restrict__ root,   // [F, F]
                 const float* __restrict__ bias,   // [F]
                 float* __restrict__ xout_p) {
    const float* __restrict__ xin = xin_p ? xin_p : g_xbuf;
    float* __restrict__ xout = xout_p ? xout_p : g_xbuf;

    __shared__ __align__(16) float As[16][128];   // [k][m]
    __shared__ __align__(16) float Bs[16][128];   // [k][n]
    __shared__ float scale_sh[128];

    const int tid = threadIdx.x;
    const int tx = tid & 15;   // output cols tx*8 .. tx*8+7
    const int ty = tid >> 4;   // output rows ty*8 .. ty*8+7
    const int row0 = blockIdx.x * 128;

    float acc[8][8];
#pragma unroll
    for (int i = 0; i < 8; ++i)
#pragma unroll
        for (int j = 0; j < 8; ++j) acc[i][j] = 0.f;

    const float* Aseg = xin;
    const float* Bseg = root;

    for (int kt = 0; kt < 40; ++kt) {            // 640 / 16
        const int seg = kt >> 3;                 // 0..4
        const int kloc = (kt & 7) << 4;

        if ((kt & 7) == 0) {
            if (seg < RR) {
                Aseg = g_aggsum + (size_t)seg * NN * FF;
                Bseg = W + (size_t)seg * FF * FF;
                if (tid < 128) {
                    int r = row0 + tid;
                    scale_sh[tid] = (r < NN)
                        ? 1.0f / fmaxf(g_cnt[(size_t)seg * NN + r], 1.0f) : 0.f;
                }
            } else {
                Aseg = xin;
                Bseg = root;
                if (tid < 128) scale_sh[tid] = 1.0f;
            }
            __syncthreads();
        }

        // A tile: 128 rows x 16 k (512 float4), transposed into smem.
#pragma unroll
        for (int t = 0; t < 2; ++t) {
            int i = tid + t * 256;
            int r = i >> 2;                 // 0..127
            int kq = (i & 3) << 2;          // 0,4,8,12
            int gr = row0 + r;
            float4 v = make_float4(0.f, 0.f, 0.f, 0.f);
            if (gr < NN)
                v = *reinterpret_cast<const float4*>(Aseg + (size_t)gr * FF + kloc + kq);
            float s = scale_sh[r];
            As[kq + 0][r] = v.x * s;
            As[kq + 1][r] = v.y * s;
            As[kq + 2][r] = v.z * s;
            As[kq + 3][r] = v.w * s;
        }

        // B tile: 16 k x 128 cols (512 float4).
#pragma unroll
        for (int t = 0; t < 2; ++t) {
            int i = tid + t * 256;
            int k = i >> 5;                 // 0..15
            int j = (i & 31) << 2;          // 0..124
            float4 v = *reinterpret_cast<const float4*>(Bseg + (size_t)(kloc + k) * FF + j);
            *reinterpret_cast<float4*>(&Bs[k][j]) = v;
        }
        __syncthreads();

#pragma unroll
        for (int k = 0; k < 16; ++k) {
            float4 a0 = *reinterpret_cast<const float4*>(&As[k][ty * 8]);
            float4 a1 = *reinterpret_cast<const float4*>(&As[k][ty * 8 + 4]);
            float4 b0 = *reinterpret_cast<const float4*>(&Bs[k][tx * 8]);
            float4 b1 = *reinterpret_cast<const float4*>(&Bs[k][tx * 8 + 4]);
            float a[8] = {a0.x, a0.y, a0.z, a0.w, a1.x, a1.y, a1.z, a1.w};
            float b[8] = {b0.x, b0.y, b0.z, b0.w, b1.x, b1.y, b1.z, b1.w};
#pragma unroll
            for (int i = 0; i < 8; ++i)
#pragma unroll
                for (int j = 0; j < 8; ++j) acc[i][j] += a[i] * b[j];
        }
        __syncthreads();
    }

    float bv[8];
#pragma unroll
    for (int j = 0; j < 8; ++j) bv[j] = bias[tx * 8 + j];

#pragma unroll
    for (int i = 0; i < 8; ++i) {
        int gr = row0 + ty * 8 + i;
        if (gr < NN) {
            float4 o0, o1;
            o0.x = fmaxf(acc[i][0] + bv[0], 0.f);
            o0.y = fmaxf(acc[i][1] + bv[1], 0.f);
            o0.z = fmaxf(acc[i][2] + bv[2], 0.f);
            o0.w = fmaxf(acc[i][3] + bv[3], 0.f);
            o1.x = fmaxf(acc[i][4] + bv[4], 0.f);
            o1.y = fmaxf(acc[i][5] + bv[5], 0.f);
            o1.z = fmaxf(acc[i][6] + bv[6], 0.f);
            o1.w = fmaxf(acc[i][7] + bv[7], 0.f);
            float* op = xout + (size_t)gr * FF + tx * 8;
            *reinterpret_cast<float4*>(op) = o0;
            *reinterpret_cast<float4*>(op + 4) = o1;
        }
    }
}

// ---------------------------------------------------------------------------
extern "C" void kernel_launch(void* const* d_in, const int* in_sizes, int n_in,
                              void* d_out, int out_size) {
    const float* x       = (const float*)d_in[0];   // [N, F] f32
    const int*   ei      = (const int*)d_in[1];     // [2, E] int32 (JAX x64 off)
    const int*   et      = (const int*)d_in[2];     // [E]    int32
    const float* weights = (const float*)d_in[3];   // [L, R, F, F]
    const float* roots   = (const float*)d_in[4];   // [L, F, F]
    const float* biases  = (const float*)d_in[5];   // [L, F]
    float* out           = (float*)d_out;           // [N, F]

    const int zero_blocks = 2048;
    const int scatter_blocks = (EE * 32 + 255) / 256;  // warp per edge
    const int gemm_blocks = (NN + 127) / 128;

    // Layer 0: x -> g_xbuf
    zero_kernel<<<zero_blocks, 256>>>();
    scatter_kernel<<<scatter_blocks, 256>>>(x, ei, et);
    gemm_kernel<<<gemm_blocks, 256>>>(x, weights, roots, biases, nullptr);

    // Layer 1: g_xbuf -> out
    zero_kernel<<<zero_blocks, 256>>>();
    scatter_kernel<<<scatter_blocks, 256>>>(nullptr, ei, et);
    gemm_kernel<<<gemm_blocks, 256>>>(nullptr,
                                      weights + (size_t)RR * FF * FF,
                                      roots + (size_t)FF * FF,
                                      biases + FF,
                                      out);
}

// round 3
// speedup vs baseline: 1.3615x; 1.3615x over previous
#include <cuda_runtime.h>
#include <cuda_bf16.h>
#include <stdint.h>

// Problem constants: N=100000 nodes, F=128 feat, R=4 relations, E=1600000, L=2.
#define NN 100000
#define FF 128
#define RR 4
#define EE 1600000
#define LL 2

// Scratch (device globals: sanctioned no-cudaMalloc workaround).
__device__ float g_aggsum[(size_t)RR * NN * FF];  // [r][n][f] feature sums
__device__ float g_cnt[(size_t)RR * NN];          // [r][n] edge counts
__device__ float g_xbuf[(size_t)NN * FF];         // inter-layer activations

// ---------------------------------------------------------------------------
__global__ void zero_kernel() {
    const size_t stride = (size_t)gridDim.x * blockDim.x;
    size_t i = (size_t)blockIdx.x * blockDim.x + threadIdx.x;
    const size_t tot4 = (size_t)RR * NN * FF / 4;
    float4 z = make_float4(0.f, 0.f, 0.f, 0.f);
    float4* agg4 = reinterpret_cast<float4*>(g_aggsum);
    for (size_t p = i; p < tot4; p += stride) agg4[p] = z;
    const size_t totc = (size_t)RR * NN;
    for (size_t p = i; p < totc; p += stride) g_cnt[p] = 0.f;
}

// ---------------------------------------------------------------------------
// Edge scatter: one warp per edge, int32 indices, fire-and-forget atomics
// (no return value -> ptxas emits REDG).
// ---------------------------------------------------------------------------
__global__ void scatter_kernel(const float* __restrict__ xin,
                               const int* __restrict__ ei,
                               const int* __restrict__ et) {
    const float* __restrict__ x = xin ? xin : g_xbuf;
    int warp = (int)(((size_t)blockIdx.x * blockDim.x + threadIdx.x) >> 5);
    int lane = threadIdx.x & 31;
    if (warp >= EE) return;

    int src = __ldg(&ei[warp]);
    int dst = __ldg(&ei[EE + warp]);
    int r   = __ldg(&et[warp]);

    const float4* xs = reinterpret_cast<const float4*>(x + (size_t)src * FF);
    float* dp = g_aggsum + ((size_t)r * NN + dst) * FF;

    float4 v = __ldg(xs + lane);
    int c = lane * 4;
    atomicAdd(dp + c + 0, v.x);
    atomicAdd(dp + c + 1, v.y);
    atomicAdd(dp + c + 2, v.z);
    atomicAdd(dp + c + 3, v.w);

    if (lane == 0) atomicAdd(&g_cnt[(size_t)r * NN + dst], 1.0f);
}

// ---------------------------------------------------------------------------
// TF32 tensor-core GEMM, fused mean + root + bias + relu.
//   out[n,:] = relu( sum_r (agg_r[n,:]/max(cnt_r[n],1)) @ W_r + x[n,:] @ root + bias )
// One [N,640] x [640,128] GEMM; virtual K = 5 segments of 128.
// BM=128, BN=128, BK=32. 256 threads = 8 warps (2 M x 4 N), warp tile 64x32,
// mma.sync.m16n8k8.tf32 with fp32 accumulate. cvt.rna.tf32 applied at smem
// store (once per element). Epilogue writes straight from accumulators.
// ---------------------------------------------------------------------------
__device__ __forceinline__ float to_tf32(float v) {
    float o;
    asm("cvt.rna.tf32.f32 %0, %1;" : "=f"(o) : "f"(v));
    return o;
}

#define ALD 36   // As leading dim (floats): row stride 36 -> bank 4q+c, conflict-free
#define BLD 132  // Bs leading dim: k stride 132 -> bank 4c+q, conflict-free

__global__ __launch_bounds__(256, 2)
void gemm_kernel(const float* __restrict__ xin_p,
                 const float* __restrict__ W,      // [R, F, F] this layer
                 const float* __restrict__ root,   // [F, F]
                 const float* __restrict__ bias,   // [F]
                 float* __restrict__ xout_p) {
    const float* __restrict__ xin = xin_p ? xin_p : g_xbuf;
    float* __restrict__ xout = xout_p ? xout_p : g_xbuf;

    __shared__ __align__(16) float As[128][ALD];  // [m][k] tf32 bits
    __shared__ __align__(16) float Bs[32][BLD];   // [k][n] tf32 bits
    __shared__ float scale_sh[128];

    const int tid = threadIdx.x;
    const int lane = tid & 31;
    const int wid = tid >> 5;          // 0..7
    const int warp_m = wid & 1;        // 0..1 -> rows warp_m*64
    const int warp_n = wid >> 1;       // 0..3 -> cols warp_n*32
    const int row0 = blockIdx.x * 128;
    const int q = lane >> 2;           // groupID 0..7
    const int c = lane & 3;            // threadID-in-group 0..3

    float acc[4][4][4];                // [mi][ni][c0..c3]
#pragma unroll
    for (int mi = 0; mi < 4; ++mi)
#pragma unroll
        for (int ni = 0; ni < 4; ++ni)
#pragma unroll
            for (int j = 0; j < 4; ++j) acc[mi][ni][j] = 0.f;

    const float* Aseg = xin;
    const float* Bseg = root;

    for (int kt = 0; kt < 20; ++kt) {          // 640 / 32
        const int seg = kt >> 2;               // 0..4
        const int kloc = (kt & 3) << 5;        // 0,32,64,96

        if ((kt & 3) == 0) {
            if (seg < RR) {
                Aseg = g_aggsum + (size_t)seg * NN * FF;
                Bseg = W + (size_t)seg * FF * FF;
                if (tid < 128) {
                    int r = row0 + tid;
                    scale_sh[tid] = (r < NN)
                        ? 1.0f / fmaxf(g_cnt[(size_t)seg * NN + r], 1.0f) : 0.f;
                }
            } else {
                Aseg = xin;
                Bseg = root;
                if (tid < 128) scale_sh[tid] = 1.0f;
            }
            __syncthreads();  // scale_sh ready before A-tile loads read it
        }

        // A tile: 128 rows x 32 k = 1024 float4; 4 per thread. Scale + tf32-cvt.
#pragma unroll
        for (int t = 0; t < 4; ++t) {
            int i = tid + t * 256;
            int r = i >> 3;                    // 0..127
            int kq = (i & 7) << 2;             // 0,4,...,28
            int gr = row0 + r;
            float4 v = make_float4(0.f, 0.f, 0.f, 0.f);
            if (gr < NN)
                v = *reinterpret_cast<const float4*>(Aseg + (size_t)gr * FF + kloc + kq);
            float s = scale_sh[r];
            float4 o;
            o.x = to_tf32(v.x * s);
            o.y = to_tf32(v.y * s);
            o.z = to_tf32(v.z * s);
            o.w = to_tf32(v.w * s);
            *reinterpret_cast<float4*>(&As[r][kq]) = o;
        }

        // B tile: 32 k x 128 n = 1024 float4; 4 per thread. tf32-cvt.
#pragma unroll
        for (int t = 0; t < 4; ++t) {
            int i = tid + t * 256;
            int k = i >> 5;                    // 0..31
            int j = (i & 31) << 2;             // 0..124
            float4 v = *reinterpret_cast<const float4*>(Bseg + (size_t)(kloc + k) * FF + j);
            float4 o;
            o.x = to_tf32(v.x);
            o.y = to_tf32(v.y);
            o.z = to_tf32(v.z);
            o.w = to_tf32(v.w);
            *reinterpret_cast<float4*>(&Bs[k][j]) = o;
        }
        __syncthreads();

        // 4 k8-steps of mma.m16n8k8 tf32.
#pragma unroll
        for (int ks = 0; ks < 4; ++ks) {
            const int kb = ks << 3;
            uint32_t a[4][4];                  // [mi][reg]
#pragma unroll
            for (int mi = 0; mi < 4; ++mi) {
                int row = warp_m * 64 + mi * 16 + q;
                const uint32_t* r0p = reinterpret_cast<const uint32_t*>(&As[row][kb + c]);
                const uint32_t* r1p = reinterpret_cast<const uint32_t*>(&As[row + 8][kb + c]);
                a[mi][0] = r0p[0];
                a[mi][1] = r1p[0];
                a[mi][2] = r0p[4];
                a[mi][3] = r1p[4];
            }
            uint32_t b[4][2];                  // [ni][reg]
#pragma unroll
            for (int ni = 0; ni < 4; ++ni) {
                int col = warp_n * 32 + ni * 8 + q;
                b[ni][0] = *reinterpret_cast<const uint32_t*>(&Bs[kb + c][col]);
                b[ni][1] = *reinterpret_cast<const uint32_t*>(&Bs[kb + c + 4][col]);
            }
#pragma unroll
            for (int mi = 0; mi < 4; ++mi)
#pragma unroll
                for (int ni = 0; ni < 4; ++ni) {
                    asm volatile(
                        "mma.sync.aligned.m16n8k8.row.col.f32.tf32.tf32.f32 "
                        "{%0,%1,%2,%3}, {%4,%5,%6,%7}, {%8,%9}, {%0,%1,%2,%3};\n"
                        : "+f"(acc[mi][ni][0]), "+f"(acc[mi][ni][1]),
                          "+f"(acc[mi][ni][2]), "+f"(acc[mi][ni][3])
                        : "r"(a[mi][0]), "r"(a[mi][1]), "r"(a[mi][2]), "r"(a[mi][3]),
                          "r"(b[ni][0]), "r"(b[ni][1]));
                }
        }
        __syncthreads();
    }

    // Epilogue: bias + relu, straight from accumulators (c-fragment layout).
#pragma unroll
    for (int ni = 0; ni < 4; ++ni) {
        int col = warp_n * 32 + ni * 8 + c * 2;
        float b0 = __ldg(&bias[col]);
        float b1 = __ldg(&bias[col + 1]);
#pragma unroll
        for (int mi = 0; mi < 4; ++mi) {
            int gr0 = row0 + warp_m * 64 + mi * 16 + q;
            if (gr0 < NN) {
                float2 o;
                o.x = fmaxf(acc[mi][ni][0] + b0, 0.f);
                o.y = fmaxf(acc[mi][ni][1] + b1, 0.f);
                *reinterpret_cast<float2*>(xout + (size_t)gr0 * FF + col) = o;
            }
            int gr1 = gr0 + 8;
            if (gr1 < NN) {
                float2 o;
                o.x = fmaxf(acc[mi][ni][2] + b0, 0.f);
                o.y = fmaxf(acc[mi][ni][3] + b1, 0.f);
                *reinterpret_cast<float2*>(xout + (size_t)gr1 * FF + col) = o;
            }
        }
    }
}

// ---------------------------------------------------------------------------
extern "C" void kernel_launch(void* const* d_in, const int* in_sizes, int n_in,
                              void* d_out, int out_size) {
    const float* x       = (const float*)d_in[0];   // [N, F] f32
    const int*   ei      = (const int*)d_in[1];     // [2, E] int32
    const int*   et      = (const int*)d_in[2];     // [E]    int32
    const float* weights = (const float*)d_in[3];   // [L, R, F, F]
    const float* roots   = (const float*)d_in[4];   // [L, F, F]
    const float* biases  = (const float*)d_in[5];   // [L, F]
    float* out           = (float*)d_out;           // [N, F]

    const int zero_blocks = 2048;
    const int scatter_blocks = (EE * 32 + 255) / 256;  // warp per edge
    const int gemm_blocks = (NN + 127) / 128;          // 782

    // Layer 0: x -> g_xbuf
    zero_kernel<<<zero_blocks, 256>>>();
    scatter_kernel<<<scatter_blocks, 256>>>(x, ei, et);
    gemm_kernel<<<gemm_blocks, 256>>>(x, weights, roots, biases, nullptr);

    // Layer 1: g_xbuf -> out
    zero_kernel<<<zero_blocks, 256>>>();
    scatter_kernel<<<scatter_blocks, 256>>>(nullptr, ei, et);
    gemm_kernel<<<gemm_blocks, 256>>>(nullptr,
                                      weights + (size_t)RR * FF * FF,
                                      roots + (size_t)FF * FF,
                                      biases + FF,
                                      out);
}

// round 5
// speedup vs baseline: 3.0578x; 2.2459x over previous
#include <cuda_runtime.h>
#include <stdint.h>

// N=100000 nodes, F=128 feat, R=4 relations, E=1600000 edges, L=2 layers.
#define NN 100000
#define FF 128
#define RR 4
#define EE 1600000
#define NB (NN * RR)                 // 400000 (dst,relation) bins, bin = r*NN + dst
#define NBLK ((NB + 1023) / 1024)    // 391 scan blocks

// Device-global scratch (no cudaMalloc allowed).
__device__ float g_agg[(size_t)RR * NN * FF];   // per-bin MEAN (tf32-rounded)
__device__ float g_xbuf[(size_t)NN * FF];       // layer-0 output (tf32-rounded)
__device__ float g_xtf[(size_t)NN * FF];        // tf32-rounded copy of input x
__device__ float g_wtf[(size_t)(RR + 1) * FF * FF];  // tf32 W[0..3] + root
__device__ int g_hist[NB];
__device__ int g_offs[NB];
__device__ int g_cursor[NB];
__device__ int g_perm[EE];                      // src indices sorted by bin
__device__ int g_bsum[NBLK];
__device__ int g_bsumx[NBLK];

__device__ __forceinline__ float to_tf32(float v) {
    float o;
    asm("cvt.rna.tf32.f32 %0, %1;" : "=f"(o) : "f"(v));
    return o;
}

// ---------------------------------------------------------------------------
// One-time prep
// ---------------------------------------------------------------------------
__global__ void convert_x_kernel(const float* __restrict__ x) {
    size_t stride = (size_t)gridDim.x * blockDim.x;
    const float4* in = reinterpret_cast<const float4*>(x);
    float4* out = reinterpret_cast<float4*>(g_xtf);
    for (size_t i = (size_t)blockIdx.x * blockDim.x + threadIdx.x;
         i < (size_t)NN * FF / 4; i += stride) {
        float4 v = in[i];
        v.x = to_tf32(v.x); v.y = to_tf32(v.y);
        v.z = to_tf32(v.z); v.w = to_tf32(v.w);
        out[i] = v;
    }
}

__global__ void hist_zero_kernel() {
    int stride = gridDim.x * blockDim.x;
    for (int i = blockIdx.x * blockDim.x + threadIdx.x; i < NB; i += stride)
        g_hist[i] = 0;
}

__global__ void hist_build_kernel(const int* __restrict__ ei,
                                  const int* __restrict__ et) {
    int e = blockIdx.x * blockDim.x + threadIdx.x;
    if (e >= EE) return;
    int dst = __ldg(&ei[EE + e]);
    int r = __ldg(&et[e]);
    atomicAdd(&g_hist[r * NN + dst], 1);
}

// Scan pass 1: per-block (1024 elems) exclusive scan + block sums.
__global__ void scan1_kernel() {
    __shared__ int sh[256];
    int t = threadIdx.x;
    int base = blockIdx.x * 1024 + t * 4;
    int v0 = (base + 0 < NB) ? g_hist[base + 0] : 0;
    int v1 = (base + 1 < NB) ? g_hist[base + 1] : 0;
    int v2 = (base + 2 < NB) ? g_hist[base + 2] : 0;
    int v3 = (base + 3 < NB) ? g_hist[base + 3] : 0;
    int s = v0 + v1 + v2 + v3;
    sh[t] = s;
    __syncthreads();
    for (int off = 1; off < 256; off <<= 1) {
        int add = (t >= off) ? sh[t - off] : 0;
        __syncthreads();
        sh[t] += add;
        __syncthreads();
    }
    int excl = sh[t] - s;
    if (base + 0 < NB) g_offs[base + 0] = excl;
    excl += v0;
    if (base + 1 < NB) g_offs[base + 1] = excl;
    excl += v1;
    if (base + 2 < NB) g_offs[base + 2] = excl;
    excl += v2;
    if (base + 3 < NB) g_offs[base + 3] = excl;
    if (t == 255) g_bsum[blockIdx.x] = sh[255];
}

// Scan pass 2: exclusive scan of block sums (single 512-thread block).
__global__ void scan2_kernel() {
    __shared__ int sh[512];
    int t = threadIdx.x;
    int v = (t < NBLK) ? g_bsum[t] : 0;
    sh[t] = v;
    __syncthreads();
    for (int off = 1; off < 512; off <<= 1) {
        int add = (t >= off) ? sh[t - off] : 0;
        __syncthreads();
        sh[t] += add;
        __syncthreads();
    }
    if (t < NBLK) g_bsumx[t] = sh[t] - v;
}

// Scan pass 3: add block offsets, init cursors.
__global__ void scan3_kernel() {
    int add = g_bsumx[blockIdx.x];
    int base = blockIdx.x * 1024 + threadIdx.x * 4;
#pragma unroll
    for (int j = 0; j < 4; ++j) {
        int i = base + j;
        if (i < NB) {
            int o = g_offs[i] + add;
            g_offs[i] = o;
            g_cursor[i] = o;
        }
    }
}

// Placement: scatter src indices into bin-sorted order.
__global__ void place_kernel(const int* __restrict__ ei,
                             const int* __restrict__ et) {
    int e = blockIdx.x * blockDim.x + threadIdx.x;
    if (e >= EE) return;
    int src = __ldg(&ei[e]);
    int dst = __ldg(&ei[EE + e]);
    int r = __ldg(&et[e]);
    int pos = atomicAdd(&g_cursor[r * NN + dst], 1);
    g_perm[pos] = src;
}

// ---------------------------------------------------------------------------
// Segmented mean aggregation: one warp per bin. No atomics, no zeroing.
// xin_sel: 0 -> external x (layer 0), 1 -> g_xbuf (layer 1).
// ---------------------------------------------------------------------------
__global__ void aggregate_kernel(const float* __restrict__ xext, int xin_sel) {
    const float* __restrict__ x = xin_sel ? g_xbuf : xext;
    int w = (int)(((size_t)blockIdx.x * blockDim.x + threadIdx.x) >> 5);
    int lane = threadIdx.x & 31;
    if (w >= NB) return;

    int start = g_offs[w];
    int cnt = g_hist[w];
    const float4* xp = reinterpret_cast<const float4*>(x);

    float4 acc = make_float4(0.f, 0.f, 0.f, 0.f);
    for (int i = 0; i < cnt; ++i) {
        int src = __ldg(&g_perm[start + i]);       // broadcast load
        float4 v = __ldg(xp + (size_t)src * 32 + lane);
        acc.x += v.x; acc.y += v.y; acc.z += v.z; acc.w += v.w;
    }
    float inv = (cnt > 0) ? 1.0f / (float)cnt : 0.f;
    float4 o;
    o.x = to_tf32(acc.x * inv);
    o.y = to_tf32(acc.y * inv);
    o.z = to_tf32(acc.z * inv);
    o.w = to_tf32(acc.w * inv);
    reinterpret_cast<float4*>(g_agg)[(size_t)w * 32 + lane] = o;
}

// ---------------------------------------------------------------------------
// Pre-round this layer's weights (W[4] then root) into g_wtf. 20480 float4.
// ---------------------------------------------------------------------------
__global__ void convert_w_kernel(const float* __restrict__ W,
                                 const float* __restrict__ root) {
    int i = blockIdx.x * blockDim.x + threadIdx.x;   // 0..20479
    const int wquads = RR * FF * FF / 4;             // 16384
    float4 v;
    if (i < wquads) v = reinterpret_cast<const float4*>(W)[i];
    else            v = reinterpret_cast<const float4*>(root)[i - wquads];
    v.x = to_tf32(v.x); v.y = to_tf32(v.y);
    v.z = to_tf32(v.z); v.w = to_tf32(v.w);
    reinterpret_cast<float4*>(g_wtf)[i] = v;
}

// ---------------------------------------------------------------------------
// TF32 tensor GEMM: out[n,:] = relu( sum_r mean_r[n,:]@W_r + xroot[n,:]@root + bias ).
// Virtual [N,640] x [640,128]; K = 5 segments of 128 (4 relation means + root).
// BM=128, BN=128, BK=16. 128 threads = 4 warps (2x2), warp tile 64x64.
// Double-buffered cp.async. All operands pre-rounded to tf32.
// xroot resolved DEVICE-SIDE from a selector (R4 bug: host-passed __device__
// symbol address is invalid).
// ---------------------------------------------------------------------------
#define A_LDF 20     // As row stride (floats)
#define B_LDF 132    // Bs row stride (floats)
#define A_BUFB (128 * A_LDF * 4)   // 10240 B
#define B_BUFB (16 * B_LDF * 4)    // 8448 B

__device__ __forceinline__ void gemm_issue(int kt, int buf, int row0,
                                           const float* __restrict__ xroot,
                                           uint32_t sA, uint32_t sB) {
    const int tid = threadIdx.x;
    const int seg = kt >> 3;              // 0..4
    const int kloc = (kt & 7) << 4;       // 0..112
    const float* Aseg = (seg < RR) ? g_agg + (size_t)seg * NN * FF : xroot;
    const float* Bseg = g_wtf + (size_t)seg * FF * FF;

    // A tile: row = tid, 4 x 16B along k. Zero-fill OOB rows via src-size 0.
    {
        int gr = row0 + tid;
        const float* src = Aseg + (size_t)gr * FF + kloc;
        uint32_t dst = sA + buf * A_BUFB + tid * (A_LDF * 4);
        int p = (gr < NN) ? 16 : 0;
#pragma unroll
        for (int c4 = 0; c4 < 4; ++c4)
            asm volatile("cp.async.cg.shared.global [%0], [%1], 16, %2;\n"
                         :: "r"(dst + 16 * c4), "l"(src + 4 * c4), "r"(p));
    }
    // B tile: 16 k x 128 n = 512 x 16B chunks, 4 per thread.
#pragma unroll
    for (int t = 0; t < 4; ++t) {
        int idx = tid + t * 128;
        int k = idx >> 5;
        int c16 = idx & 31;
        const float* src = Bseg + (size_t)(kloc + k) * FF + c16 * 4;
        uint32_t dst = sB + buf * B_BUFB + k * (B_LDF * 4) + c16 * 16;
        asm volatile("cp.async.cg.shared.global [%0], [%1], 16;\n"
                     :: "r"(dst), "l"(src));
    }
}

__global__ __launch_bounds__(128, 2)
void gemm_kernel(int xroot_sel,                   // 0 -> g_xtf, 1 -> g_xbuf
                 const float* __restrict__ bias,
                 float* __restrict__ xout_p,      // nullptr -> g_xbuf
                 int round_out) {
    const float* __restrict__ xroot = xroot_sel ? g_xbuf : g_xtf;
    float* __restrict__ xout = xout_p ? xout_p : g_xbuf;

    __shared__ __align__(16) float As[2][128][A_LDF];
    __shared__ __align__(16) float Bs[2][16][B_LDF];
    uint32_t sA = (uint32_t)__cvta_generic_to_shared(&As[0][0][0]);
    uint32_t sB = (uint32_t)__cvta_generic_to_shared(&Bs[0][0][0]);

    const int tid = threadIdx.x;
    const int lane = tid & 31;
    const int wid = tid >> 5;        // 0..3
    const int warp_m = wid & 1;      // rows warp_m*64
    const int warp_n = wid >> 1;     // cols warp_n*64
    const int q = lane >> 2;         // 0..7
    const int c = lane & 3;          // 0..3
    const int row0 = blockIdx.x * 128;

    float acc[4][8][4];
#pragma unroll
    for (int mi = 0; mi < 4; ++mi)
#pragma unroll
        for (int ni = 0; ni < 8; ++ni)
#pragma unroll
            for (int j = 0; j < 4; ++j) acc[mi][ni][j] = 0.f;

    gemm_issue(0, 0, row0, xroot, sA, sB);
    asm volatile("cp.async.commit_group;\n" ::: "memory");

    for (int kt = 0; kt < 40; ++kt) {
        if (kt + 1 < 40)
            gemm_issue(kt + 1, (kt + 1) & 1, row0, xroot, sA, sB);
        asm volatile("cp.async.commit_group;\n" ::: "memory");
        asm volatile("cp.async.wait_group 1;\n" ::: "memory");
        __syncthreads();

        const int buf = kt & 1;
#pragma unroll
        for (int ks = 0; ks < 2; ++ks) {
            const int kb = ks << 3;
            uint32_t a[4][4];
#pragma unroll
            for (int mi = 0; mi < 4; ++mi) {
                int row = warp_m * 64 + mi * 16 + q;
                a[mi][0] = __float_as_uint(As[buf][row][kb + c]);
                a[mi][1] = __float_as_uint(As[buf][row + 8][kb + c]);
                a[mi][2] = __float_as_uint(As[buf][row][kb + c + 4]);
                a[mi][3] = __float_as_uint(As[buf][row + 8][kb + c + 4]);
            }
            uint32_t b[8][2];
#pragma unroll
            for (int ni = 0; ni < 8; ++ni) {
                int col = warp_n * 64 + ni * 8 + q;
                b[ni][0] = __float_as_uint(Bs[buf][kb + c][col]);
                b[ni][1] = __float_as_uint(Bs[buf][kb + c + 4][col]);
            }
#pragma unroll
            for (int mi = 0; mi < 4; ++mi)
#pragma unroll
                for (int ni = 0; ni < 8; ++ni) {
                    asm volatile(
                        "mma.sync.aligned.m16n8k8.row.col.f32.tf32.tf32.f32 "
                        "{%0,%1,%2,%3}, {%4,%5,%6,%7}, {%8,%9}, {%0,%1,%2,%3};\n"
                        : "+f"(acc[mi][ni][0]), "+f"(acc[mi][ni][1]),
                          "+f"(acc[mi][ni][2]), "+f"(acc[mi][ni][3])
                        : "r"(a[mi][0]), "r"(a[mi][1]), "r"(a[mi][2]), "r"(a[mi][3]),
                          "r"(b[ni][0]), "r"(b[ni][1]));
                }
        }
        __syncthreads();
    }

    // Epilogue: bias + relu; tf32-round when feeding layer 1.
#pragma unroll
    for (int ni = 0; ni < 8; ++ni) {
        int col = warp_n * 64 + ni * 8 + c * 2;
        float b0 = __ldg(&bias[col]);
        float b1 = __ldg(&bias[col + 1]);
#pragma unroll
        for (int mi = 0; mi < 4; ++mi) {
            int gr0 = row0 + warp_m * 64 + mi * 16 + q;
            if (gr0 < NN) {
                float2 o;
                o.x = fmaxf(acc[mi][ni][0] + b0, 0.f);
                o.y = fmaxf(acc[mi][ni][1] + b1, 0.f);
                if (round_out) { o.x = to_tf32(o.x); o.y = to_tf32(o.y); }
                *reinterpret_cast<float2*>(xout + (size_t)gr0 * FF + col) = o;
            }
            int gr1 = gr0 + 8;
            if (gr1 < NN) {
                float2 o;
                o.x = fmaxf(acc[mi][ni][2] + b0, 0.f);
                o.y = fmaxf(acc[mi][ni][3] + b1, 0.f);
                if (round_out) { o.x = to_tf32(o.x); o.y = to_tf32(o.y); }
                *reinterpret_cast<float2*>(xout + (size_t)gr1 * FF + col) = o;
            }
        }
    }
}

// ---------------------------------------------------------------------------
extern "C" void kernel_launch(void* const* d_in, const int* in_sizes, int n_in,
                              void* d_out, int out_size) {
    const float* x       = (const float*)d_in[0];   // [N, F] f32
    const int*   ei      = (const int*)d_in[1];     // [2, E] int32
    const int*   et      = (const int*)d_in[2];     // [E]    int32
    const float* weights = (const float*)d_in[3];   // [L, R, F, F]
    const float* roots   = (const float*)d_in[4];   // [L, F, F]
    const float* biases  = (const float*)d_in[5];   // [L, F]
    float* out           = (float*)d_out;           // [N, F]

    const int edge_blocks = (EE + 255) / 256;            // 6250
    const int agg_blocks  = (NB * 32 + 255) / 256;       // 50000
    const int gemm_blocks = (NN + 127) / 128;            // 782

    // One-time: tf32 x copy + counting sort of edges by (relation, dst).
    convert_x_kernel<<<1024, 256>>>(x);
    hist_zero_kernel<<<512, 256>>>();
    hist_build_kernel<<<edge_blocks, 256>>>(ei, et);
    scan1_kernel<<<NBLK, 256>>>();
    scan2_kernel<<<1, 512>>>();
    scan3_kernel<<<NBLK, 256>>>();
    place_kernel<<<edge_blocks, 256>>>(ei, et);

    // Layer 0: x -> g_xbuf
    aggregate_kernel<<<agg_blocks, 256>>>(x, 0);
    convert_w_kernel<<<80, 256>>>(weights, roots);
    gemm_kernel<<<gemm_blocks, 128>>>(0, biases, nullptr, 1);

    // Layer 1: g_xbuf -> out
    aggregate_kernel<<<agg_blocks, 256>>>(nullptr, 1);
    convert_w_kernel<<<80, 256>>>(weights + (size_t)RR * FF * FF,
                                  roots + (size_t)FF * FF);
    gemm_kernel<<<gemm_blocks, 128>>>(1, biases + FF, out, 0);
}